// round 1
// baseline (speedup 1.0000x reference)
#include <cuda_runtime.h>
#include <cstdint>

#define B_  8
#define T_  128
#define NH_ 8
#define CI_ 16
#define CO_ 32
#define H_  32
#define W_  64
#define L_  (H_*W_)          // 2048
#define BN_EPS_ 1e-5f

#define TILE_H 8
#define SIN_ROWS 12
#define SIN_COLS 68
#define SMEM_IN_F (CI_*SIN_ROWS*SIN_COLS)   // 13056 floats
#define SMEM_W_F  (CI_*25*CO_)              // 12800 floats
// smem layout (floats): [0,13056) s_in | [13056,25856) s_w | [25856,26112) s_pw
//                       [26112,26144) s_cb | [26144,26161) s_red
// s_stage (8*512=4096) aliases s_in after a __syncthreads()
#define SMEM_TOTAL_F (SMEM_IN_F + SMEM_W_F + 256 + 32 + 17)

// ---------------- scratch (static device arrays: no runtime alloc) ----------
__device__ float g_cumsum[(size_t)B_*T_*CI_*L_];   // (bt, ci, pix)  128 MiB
__device__ float g_cov[(size_t)B_*NH_*T_*L_];      // final layout (b,n,t,pix) 64 MiB
__device__ float g_sum[NH_];
__device__ float g_sumsq[NH_];
__device__ float g_cnt;

// ---------------- kernel 0: zero BN accumulators ----------------------------
__global__ void k_zero() {
    int i = threadIdx.x;
    if (i < NH_) { g_sum[i] = 0.f; g_sumsq[i] = 0.f; }
    if (i == 0)  g_cnt = 0.f;
}

// ---------------- kernel 1: exclusive cumsum over t --------------------------
// grid (8 pix-chunks, 16 ci, 8 b), 256 threads; thread owns one (b,ci,pix) line
__global__ void __launch_bounds__(256) k_cumsum(const float* __restrict__ prev,
                                                const float* __restrict__ curr)
{
    int pix = blockIdx.x * 256 + threadIdx.x;   // 0..2047
    int ci  = blockIdx.y;                       // 0..15
    int b   = blockIdx.z;                       // 0..7
    const float* src = (ci < NH_)
        ? (prev + ((size_t)(b*NH_ + ci))      * T_ * L_)
        : (curr + ((size_t)(b*NH_ + ci - NH_))* T_ * L_);
    src += pix;
    size_t obase   = (((size_t)b*T_)*CI_ + ci) * L_ + pix;
    const size_t ostride = (size_t)CI_ * L_;    // per-t stride in cumsum layout
    float run = 0.f;
    #pragma unroll 4
    for (int t = 0; t < T_; t++) {
        g_cumsum[obase + (size_t)t * ostride] = run;
        run += src[(size_t)t * L_];
    }
}

// ---------------- kernel 2: conv5x5 + bias + relu + mask + 1x1 proj + sums ---
// grid (4 h-tiles, 1024 bt), 256 threads.
// warp wid = row-in-tile; lane: xg = lane&7 (8-col group), ocg = lane>>3 (8-oc group)
__global__ void __launch_bounds__(256) k_conv(const float* __restrict__ conv_w,
                                              const float* __restrict__ conv_b,
                                              const float* __restrict__ proj_w,
                                              const int*   __restrict__ mask)
{
    extern __shared__ float smem[];
    float* s_in    = smem;                         // 13056
    float* s_w     = smem + SMEM_IN_F;             // 12800
    float* s_pw    = s_w + SMEM_W_F;               // 256
    float* s_cb    = s_pw + 256;                   // 32
    float* s_red   = s_cb + 32;                    // 17: sum[8], sq[8], cnt
    float* s_stage = smem;                         // aliases s_in (post-sync)

    const int tid  = threadIdx.x;
    const int tile = blockIdx.x;                   // 0..3
    const int bt   = blockIdx.y;                   // 0..1023
    const int b    = bt >> 7;
    const int t    = bt & 127;

    // ---- load conv weights (tap-major, oc consecutive) ----
    // s_w[tap*32 + oc] = conv_w[oc*400 + tap]
    for (int i = tid; i < SMEM_W_F; i += 256)
        s_w[i] = conv_w[(i & 31) * 400 + (i >> 5)];
    for (int i = tid; i < NH_*CO_; i += 256) s_pw[i] = proj_w[i];
    if (tid < CO_) s_cb[tid] = conv_b[tid];
    if (tid < 17)  s_red[tid] = 0.f;

    // ---- load input tile with halo (zero-padded) ----
    const float* gin = g_cumsum + (size_t)bt * CI_ * L_;
    const int row0 = tile * TILE_H - 2;
    for (int i = tid; i < SMEM_IN_F; i += 256) {
        int ci  = i / (SIN_ROWS * SIN_COLS);
        int rem = i - ci * (SIN_ROWS * SIN_COLS);
        int r   = rem / SIN_COLS;
        int c   = rem - r * SIN_COLS;
        int gr  = row0 + r;
        int gc  = c - 2;
        float v = 0.f;
        if ((unsigned)gr < (unsigned)H_ && (unsigned)gc < (unsigned)W_)
            v = gin[(size_t)ci * L_ + gr * W_ + gc];
        s_in[i] = v;
    }
    __syncthreads();

    const int wid  = tid >> 5;        // row within tile 0..7
    const int lane = tid & 31;
    const int xg   = lane & 7;        // column group (8 px)
    const int ocg  = lane >> 3;       // oc group (8 oc)
    const int colbase = xg * 8;
    const int ocbase  = ocg * 8;

    // f32x2 accumulators: acc[o2][px] holds (oc=ocbase+2*o2, oc+1)
    unsigned long long acc[4][8];
    #pragma unroll
    for (int a = 0; a < 4; a++)
        #pragma unroll
        for (int p = 0; p < 8; p++) acc[a][p] = 0ull;

    #pragma unroll 1
    for (int ci = 0; ci < CI_; ci++) {
        #pragma unroll
        for (int ky = 0; ky < 5; ky++) {
            const float* rp = s_in + (ci * SIN_ROWS + wid + ky) * SIN_COLS + colbase;
            float4 A = *(const float4*)(rp);
            float4 Bv = *(const float4*)(rp + 4);
            float4 Cv = *(const float4*)(rp + 8);
            float inr[12] = {A.x,A.y,A.z,A.w, Bv.x,Bv.y,Bv.z,Bv.w, Cv.x,Cv.y,Cv.z,Cv.w};
            unsigned long long in2[12];
            #pragma unroll
            for (int i = 0; i < 12; i++)
                asm("mov.b64 %0, {%1, %1};" : "=l"(in2[i]) : "f"(inr[i]));
            #pragma unroll
            for (int kx = 0; kx < 5; kx++) {
                const ulonglong2* wp =
                    (const ulonglong2*)(s_w + ((ci*5 + ky)*5 + kx) * CO_ + ocbase);
                ulonglong2 w01 = wp[0];
                ulonglong2 w23 = wp[1];
                unsigned long long w2[4] = {w01.x, w01.y, w23.x, w23.y};
                #pragma unroll
                for (int p = 0; p < 8; p++) {
                    #pragma unroll
                    for (int o2 = 0; o2 < 4; o2++)
                        asm("fma.rn.f32x2 %0, %1, %2, %0;"
                            : "+l"(acc[o2][p]) : "l"(w2[o2]), "l"(in2[p + kx]));
                }
            }
        }
    }

    // ---- bias + relu + mask, stream into 1x1 proj partials ----
    const int grow = tile * TILE_H + wid;
    const int* mrow = mask + b * L_ + grow * W_ + colbase;
    int m[8];
    #pragma unroll
    for (int p = 0; p < 8; p++) m[p] = mrow[p];

    float part[8][8];   // [n][px] partial over this thread's 8 oc
    #pragma unroll
    for (int n = 0; n < 8; n++)
        #pragma unroll
        for (int p = 0; p < 8; p++) part[n][p] = 0.f;

    #pragma unroll
    for (int o2 = 0; o2 < 4; o2++) {
        float cb0 = s_cb[ocbase + 2*o2];
        float cb1 = s_cb[ocbase + 2*o2 + 1];
        float pw0[8], pw1[8];
        #pragma unroll
        for (int n = 0; n < 8; n++) {
            pw0[n] = s_pw[n * CO_ + ocbase + 2*o2];
            pw1[n] = s_pw[n * CO_ + ocbase + 2*o2 + 1];
        }
        #pragma unroll
        for (int p = 0; p < 8; p++) {
            float lo, hi;
            asm("mov.b64 {%0, %1}, %2;" : "=f"(lo), "=f"(hi) : "l"(acc[o2][p]));
            float v0 = fmaxf(lo + cb0, 0.f);
            float v1 = fmaxf(hi + cb1, 0.f);
            if (m[p]) { v0 = 0.f; v1 = 0.f; }
            #pragma unroll
            for (int n = 0; n < 8; n++) {
                part[n][p] = fmaf(pw0[n], v0, part[n][p]);
                part[n][p] = fmaf(pw1[n], v1, part[n][p]);
            }
        }
    }

    // ---- reduce over the 4 oc-groups (lane bits 3,4) ----
    #pragma unroll
    for (int n = 0; n < 8; n++)
        #pragma unroll
        for (int p = 0; p < 8; p++) {
            float v = part[n][p];
            v += __shfl_xor_sync(0xffffffffu, v, 8);
            v += __shfl_xor_sync(0xffffffffu, v, 16);
            part[n][p] = v;
        }

    __syncthreads();   // all conv-phase s_in reads done; safe to alias s_stage

    if (ocg == 0) {    // lanes 0..7 hold final cov for (row=wid, cols xg*8..+7)
        int cnt = 0;
        #pragma unroll
        for (int p = 0; p < 8; p++) cnt += (m[p] == 0);
        #pragma unroll
        for (int n = 0; n < 8; n++) {
            float s = 0.f, q = 0.f;
            #pragma unroll
            for (int p = 0; p < 8; p++) {
                float v = part[n][p];
                s += v; q += v * v;
                s_stage[n * 512 + wid * 64 + xg * 8 + p] = v;
            }
            atomicAdd(&s_red[n],     s);
            atomicAdd(&s_red[8 + n], q);
        }
        atomicAdd(&s_red[16], (float)cnt);
    }
    __syncthreads();

    if (tid < NH_) {
        atomicAdd(&g_sum[tid],   s_red[tid]);
        atomicAdd(&g_sumsq[tid], s_red[8 + tid]);
    }
    if (tid == NH_) atomicAdd(&g_cnt, s_red[16]);

    // ---- coalesced store in final (b,n,t,pix) layout ----
    for (int i = tid; i < NH_ * 512; i += 256) {
        int n = i >> 9;
        int p = i & 511;
        g_cov[(((size_t)(b * NH_ + n)) * T_ + t) * L_ + tile * 512 + p] = s_stage[i];
    }
}

// ---------------- kernel 3: masked batch-norm epilogue -----------------------
__global__ void __launch_bounds__(256) k_final(float* __restrict__ out,
                                               const int* __restrict__ mask,
                                               const float* __restrict__ gamma,
                                               const float* __restrict__ beta)
{
    __shared__ float s_scale[NH_], s_shift[NH_];
    if (threadIdx.x < NH_) {
        int n = threadIdx.x;
        float cnt  = fmaxf(g_cnt, 1.f);
        float mean = g_sum[n] / cnt;
        float var  = fmaxf(g_sumsq[n] / cnt - mean * mean, 0.f);
        float sc   = gamma[n] * rsqrtf(var + BN_EPS_);
        s_scale[n] = sc;
        s_shift[n] = beta[n] - mean * sc;
    }
    __syncthreads();

    size_t base = ((size_t)blockIdx.x * 256 + threadIdx.x) * 4;
    const size_t total = (size_t)B_ * NH_ * T_ * L_;
    if (base >= total) return;
    int n   = (int)((base >> 18) & 7);   // T_*L_ = 2^18
    int b   = (int)(base >> 21);         // NH_*T_*L_ = 2^21
    int pix = (int)(base & (L_ - 1));

    float4 v = *(const float4*)(g_cov + base);
    int4  mv = *(const int4*)(mask + b * L_ + pix);
    float sc = s_scale[n], sh = s_shift[n];
    float4 o;
    o.x = mv.x ? 0.f : fmaf(v.x, sc, sh);
    o.y = mv.y ? 0.f : fmaf(v.y, sc, sh);
    o.z = mv.z ? 0.f : fmaf(v.z, sc, sh);
    o.w = mv.w ? 0.f : fmaf(v.w, sc, sh);
    *(float4*)(out + base) = o;
}

// ---------------- launch ------------------------------------------------------
extern "C" void kernel_launch(void* const* d_in, const int* in_sizes, int n_in,
                              void* d_out, int out_size)
{
    const float* prev   = (const float*)d_in[0];
    const float* curr   = (const float*)d_in[1];
    const int*   mask   = (const int*)  d_in[2];   // bool promoted to int32
    // d_in[3] = h (unused, compile-time 32)
    const float* conv_w = (const float*)d_in[4];
    const float* conv_b = (const float*)d_in[5];
    const float* proj_w = (const float*)d_in[6];
    const float* gamma  = (const float*)d_in[7];
    const float* beta   = (const float*)d_in[8];
    float* out = (float*)d_out;

    const int smem_bytes = SMEM_TOTAL_F * (int)sizeof(float);   // ~104.6 KB
    cudaFuncSetAttribute(k_conv, cudaFuncAttributeMaxDynamicSharedMemorySize,
                         smem_bytes);

    k_zero<<<1, 32>>>();
    k_cumsum<<<dim3(L_/256, CI_, B_), 256>>>(prev, curr);
    k_conv<<<dim3(H_/TILE_H, B_*T_), 256, smem_bytes>>>(conv_w, conv_b, proj_w, mask);
    const size_t total = (size_t)B_ * NH_ * T_ * L_;
    k_final<<<(unsigned)(total / 4 / 256), 256>>>(out, mask, gamma, beta);
}

// round 3
// speedup vs baseline: 1.0011x; 1.0011x over previous
#include <cuda_runtime.h>
#include <cstdint>

#define B_  8
#define T_  128
#define NH_ 8
#define CI_ 16
#define CO_ 32
#define H_  32
#define W_  64
#define L_  (H_*W_)          // 2048
#define BN_EPS_ 1e-5f

#define TILE_H 8
#define SIN_ROWS 12
#define SIN_COLS 68
#define SMEM_IN_F (CI_*SIN_ROWS*SIN_COLS)   // 13056 floats
#define SMEM_W_F  (CI_*25*CO_)              // 12800 floats
// smem layout (floats): [0,13056) s_in | [13056,25856) s_w | [25856,26112) s_pw
//                       [26112,26144) s_cb | [26144,26161) s_red
// s_stage (8*512=4096) aliases s_in after a __syncthreads()
#define SMEM_TOTAL_F (SMEM_IN_F + SMEM_W_F + 256 + 32 + 17)

// ---------------- scratch (static device arrays: no runtime alloc) ----------
__device__ float g_cumsum[(size_t)B_*T_*CI_*L_];   // (bt, ci, pix)  128 MiB
__device__ float g_cov[(size_t)B_*NH_*T_*L_];      // final layout (b,n,t,pix) 64 MiB
__device__ float g_sum[NH_];
__device__ float g_sumsq[NH_];
__device__ float g_cnt;

// ---------------- kernel 0: zero BN accumulators ----------------------------
__global__ void k_zero() {
    int i = threadIdx.x;
    if (i < NH_) { g_sum[i] = 0.f; g_sumsq[i] = 0.f; }
    if (i == 0)  g_cnt = 0.f;
}

// ---------------- kernel 1: exclusive cumsum over t --------------------------
// grid (8 pix-chunks, 16 ci, 8 b), 256 threads; thread owns one (b,ci,pix) line
__global__ void __launch_bounds__(256) k_cumsum(const float* __restrict__ prev,
                                                const float* __restrict__ curr)
{
    int pix = blockIdx.x * 256 + threadIdx.x;   // 0..2047
    int ci  = blockIdx.y;                       // 0..15
    int b   = blockIdx.z;                       // 0..7
    const float* src = (ci < NH_)
        ? (prev + ((size_t)(b*NH_ + ci))      * T_ * L_)
        : (curr + ((size_t)(b*NH_ + ci - NH_))* T_ * L_);
    src += pix;
    size_t obase   = (((size_t)b*T_)*CI_ + ci) * L_ + pix;
    const size_t ostride = (size_t)CI_ * L_;    // per-t stride in cumsum layout
    float run = 0.f;
    #pragma unroll 4
    for (int t = 0; t < T_; t++) {
        g_cumsum[obase + (size_t)t * ostride] = run;
        run += src[(size_t)t * L_];
    }
}

// ---------------- kernel 2: conv5x5 + bias + relu + mask + 1x1 proj + sums ---
// grid (4 h-tiles, 1024 bt), 256 threads.
// warp wid = row-in-tile; lane: xg = lane&7 (8-col group), ocg = lane>>3 (8-oc group)
__global__ void __launch_bounds__(256) k_conv(const float* __restrict__ conv_w,
                                              const float* __restrict__ conv_b,
                                              const float* __restrict__ proj_w,
                                              const int*   __restrict__ mask)
{
    extern __shared__ float smem[];
    float* s_in    = smem;                         // 13056
    float* s_w     = smem + SMEM_IN_F;             // 12800
    float* s_pw    = s_w + SMEM_W_F;               // 256
    float* s_cb    = s_pw + 256;                   // 32
    float* s_red   = s_cb + 32;                    // 17: sum[8], sq[8], cnt
    float* s_stage = smem;                         // aliases s_in (post-sync)

    const int tid  = threadIdx.x;
    const int tile = blockIdx.x;                   // 0..3
    const int bt   = blockIdx.y;                   // 0..1023
    const int b    = bt >> 7;
    const int t    = bt & 127;

    // ---- load conv weights (tap-major, oc consecutive) ----
    // s_w[tap*32 + oc] = conv_w[oc*400 + tap]
    for (int i = tid; i < SMEM_W_F; i += 256)
        s_w[i] = conv_w[(i & 31) * 400 + (i >> 5)];
    for (int i = tid; i < NH_*CO_; i += 256) s_pw[i] = proj_w[i];
    if (tid < CO_) s_cb[tid] = conv_b[tid];
    if (tid < 17)  s_red[tid] = 0.f;

    // ---- load input tile with halo (zero-padded) ----
    const float* gin = g_cumsum + (size_t)bt * CI_ * L_;
    const int row0 = tile * TILE_H - 2;
    for (int i = tid; i < SMEM_IN_F; i += 256) {
        int ci  = i / (SIN_ROWS * SIN_COLS);
        int rem = i - ci * (SIN_ROWS * SIN_COLS);
        int r   = rem / SIN_COLS;
        int c   = rem - r * SIN_COLS;
        int gr  = row0 + r;
        int gc  = c - 2;
        float v = 0.f;
        if ((unsigned)gr < (unsigned)H_ && (unsigned)gc < (unsigned)W_)
            v = gin[(size_t)ci * L_ + gr * W_ + gc];
        s_in[i] = v;
    }
    __syncthreads();

    const int wid  = tid >> 5;        // row within tile 0..7
    const int lane = tid & 31;
    const int xg   = lane & 7;        // column group (8 px)
    const int ocg  = lane >> 3;       // oc group (8 oc)
    const int colbase = xg * 8;
    const int ocbase  = ocg * 8;

    // f32x2 accumulators: acc[o2][px] holds (oc=ocbase+2*o2, oc+1)
    unsigned long long acc[4][8];
    #pragma unroll
    for (int a = 0; a < 4; a++)
        #pragma unroll
        for (int p = 0; p < 8; p++) acc[a][p] = 0ull;

    #pragma unroll 1
    for (int ci = 0; ci < CI_; ci++) {
        #pragma unroll
        for (int ky = 0; ky < 5; ky++) {
            const float* rp = s_in + (ci * SIN_ROWS + wid + ky) * SIN_COLS + colbase;
            float4 A = *(const float4*)(rp);
            float4 Bv = *(const float4*)(rp + 4);
            float4 Cv = *(const float4*)(rp + 8);
            float inr[12] = {A.x,A.y,A.z,A.w, Bv.x,Bv.y,Bv.z,Bv.w, Cv.x,Cv.y,Cv.z,Cv.w};
            unsigned long long in2[12];
            #pragma unroll
            for (int i = 0; i < 12; i++)
                asm("mov.b64 %0, {%1, %1};" : "=l"(in2[i]) : "f"(inr[i]));
            #pragma unroll
            for (int kx = 0; kx < 5; kx++) {
                const ulonglong2* wp =
                    (const ulonglong2*)(s_w + ((ci*5 + ky)*5 + kx) * CO_ + ocbase);
                ulonglong2 w01 = wp[0];
                ulonglong2 w23 = wp[1];
                unsigned long long w2[4] = {w01.x, w01.y, w23.x, w23.y};
                #pragma unroll
                for (int p = 0; p < 8; p++) {
                    #pragma unroll
                    for (int o2 = 0; o2 < 4; o2++)
                        asm("fma.rn.f32x2 %0, %1, %2, %0;"
                            : "+l"(acc[o2][p]) : "l"(w2[o2]), "l"(in2[p + kx]));
                }
            }
        }
    }

    // ---- bias + relu + mask, stream into 1x1 proj partials ----
    const int grow = tile * TILE_H + wid;
    const int* mrow = mask + b * L_ + grow * W_ + colbase;
    int m[8];
    #pragma unroll
    for (int p = 0; p < 8; p++) m[p] = mrow[p];

    float part[8][8];   // [n][px] partial over this thread's 8 oc
    #pragma unroll
    for (int n = 0; n < 8; n++)
        #pragma unroll
        for (int p = 0; p < 8; p++) part[n][p] = 0.f;

    #pragma unroll
    for (int o2 = 0; o2 < 4; o2++) {
        float cb0 = s_cb[ocbase + 2*o2];
        float cb1 = s_cb[ocbase + 2*o2 + 1];
        float pw0[8], pw1[8];
        #pragma unroll
        for (int n = 0; n < 8; n++) {
            pw0[n] = s_pw[n * CO_ + ocbase + 2*o2];
            pw1[n] = s_pw[n * CO_ + ocbase + 2*o2 + 1];
        }
        #pragma unroll
        for (int p = 0; p < 8; p++) {
            float lo, hi;
            asm("mov.b64 {%0, %1}, %2;" : "=f"(lo), "=f"(hi) : "l"(acc[o2][p]));
            float v0 = fmaxf(lo + cb0, 0.f);
            float v1 = fmaxf(hi + cb1, 0.f);
            if (m[p]) { v0 = 0.f; v1 = 0.f; }
            #pragma unroll
            for (int n = 0; n < 8; n++) {
                part[n][p] = fmaf(pw0[n], v0, part[n][p]);
                part[n][p] = fmaf(pw1[n], v1, part[n][p]);
            }
        }
    }

    // ---- reduce over the 4 oc-groups (lane bits 3,4) ----
    #pragma unroll
    for (int n = 0; n < 8; n++)
        #pragma unroll
        for (int p = 0; p < 8; p++) {
            float v = part[n][p];
            v += __shfl_xor_sync(0xffffffffu, v, 8);
            v += __shfl_xor_sync(0xffffffffu, v, 16);
            part[n][p] = v;
        }

    __syncthreads();   // all conv-phase s_in reads done; safe to alias s_stage

    if (ocg == 0) {    // lanes 0..7 hold final cov for (row=wid, cols xg*8..+7)
        int cnt = 0;
        #pragma unroll
        for (int p = 0; p < 8; p++) cnt += (m[p] == 0);
        #pragma unroll
        for (int n = 0; n < 8; n++) {
            float s = 0.f, q = 0.f;
            #pragma unroll
            for (int p = 0; p < 8; p++) {
                float v = part[n][p];
                s += v; q += v * v;
                s_stage[n * 512 + wid * 64 + xg * 8 + p] = v;
            }
            atomicAdd(&s_red[n],     s);
            atomicAdd(&s_red[8 + n], q);
        }
        atomicAdd(&s_red[16], (float)cnt);
    }
    __syncthreads();

    if (tid < NH_) {
        atomicAdd(&g_sum[tid],   s_red[tid]);
        atomicAdd(&g_sumsq[tid], s_red[8 + tid]);
    }
    if (tid == NH_) atomicAdd(&g_cnt, s_red[16]);

    // ---- coalesced store in final (b,n,t,pix) layout ----
    for (int i = tid; i < NH_ * 512; i += 256) {
        int n = i >> 9;
        int p = i & 511;
        g_cov[(((size_t)(b * NH_ + n)) * T_ + t) * L_ + tile * 512 + p] = s_stage[i];
    }
}

// ---------------- kernel 3: masked batch-norm epilogue -----------------------
__global__ void __launch_bounds__(256) k_final(float* __restrict__ out,
                                               const int* __restrict__ mask,
                                               const float* __restrict__ gamma,
                                               const float* __restrict__ beta)
{
    __shared__ float s_scale[NH_], s_shift[NH_];
    if (threadIdx.x < NH_) {
        int n = threadIdx.x;
        float cnt  = fmaxf(g_cnt, 1.f);
        float mean = g_sum[n] / cnt;
        float var  = fmaxf(g_sumsq[n] / cnt - mean * mean, 0.f);
        float sc   = gamma[n] * rsqrtf(var + BN_EPS_);
        s_scale[n] = sc;
        s_shift[n] = beta[n] - mean * sc;
    }
    __syncthreads();

    size_t base = ((size_t)blockIdx.x * 256 + threadIdx.x) * 4;
    const size_t total = (size_t)B_ * NH_ * T_ * L_;
    if (base >= total) return;
    int n   = (int)((base >> 18) & 7);   // T_*L_ = 2^18
    int b   = (int)(base >> 21);         // NH_*T_*L_ = 2^21
    int pix = (int)(base & (L_ - 1));

    float4 v = *(const float4*)(g_cov + base);
    int4  mv = *(const int4*)(mask + b * L_ + pix);
    float sc = s_scale[n], sh = s_shift[n];
    float4 o;
    o.x = mv.x ? 0.f : fmaf(v.x, sc, sh);
    o.y = mv.y ? 0.f : fmaf(v.y, sc, sh);
    o.z = mv.z ? 0.f : fmaf(v.z, sc, sh);
    o.w = mv.w ? 0.f : fmaf(v.w, sc, sh);
    *(float4*)(out + base) = o;
}

// ---------------- launch ------------------------------------------------------
extern "C" void kernel_launch(void* const* d_in, const int* in_sizes, int n_in,
                              void* d_out, int out_size)
{
    const float* prev   = (const float*)d_in[0];
    const float* curr   = (const float*)d_in[1];
    const int*   mask   = (const int*)  d_in[2];   // bool promoted to int32
    // d_in[3] = h (unused, compile-time 32)
    const float* conv_w = (const float*)d_in[4];
    const float* conv_b = (const float*)d_in[5];
    const float* proj_w = (const float*)d_in[6];
    const float* gamma  = (const float*)d_in[7];
    const float* beta   = (const float*)d_in[8];
    float* out = (float*)d_out;

    const int smem_bytes = SMEM_TOTAL_F * (int)sizeof(float);   // ~104.6 KB
    cudaFuncSetAttribute(k_conv, cudaFuncAttributeMaxDynamicSharedMemorySize,
                         smem_bytes);

    k_zero<<<1, 32>>>();
    k_cumsum<<<dim3(L_/256, CI_, B_), 256>>>(prev, curr);
    k_conv<<<dim3(H_/TILE_H, B_*T_), 256, smem_bytes>>>(conv_w, conv_b, proj_w, mask);
    const size_t total = (size_t)B_ * NH_ * T_ * L_;
    k_final<<<(unsigned)(total / 4 / 256), 256>>>(out, mask, gamma, beta);
}